// round 4
// baseline (speedup 1.0000x reference)
#include <cuda_runtime.h>
#include <cstdint>

#define NUM_CLASSES 100000
#define FEAT_DIM    256
#define BATCH       8192
#define ALPHA_C     1.0f
#define EPS_C       1e-6f

#define FUSED_BLOCKS (NUM_CLASSES / 8)   // 12500 blocks * 8 warps = 100000 classes

// Scratch (no cudaMalloc allowed)
__device__ int   g_counts[NUM_CLASSES];
__device__ int   g_head[NUM_CLASSES];   // first sample index per class, -1 if none
__device__ int   g_next[BATCH];         // linked list of samples per class
__device__ float g_loss_part[256];
__device__ unsigned int g_done;

// ---------------------------------------------------------------------------
// K0: zero scratch
__global__ void k_zero() {
    int i = blockIdx.x * blockDim.x + threadIdx.x;
    if (i == 0) g_done = 0;
    if (i < 256) g_loss_part[i] = 0.0f;
    if (i < NUM_CLASSES) { g_counts[i] = 0; g_head[i] = -1; }
}

// K1: counts + per-class sample linked lists (8192 cheap atomics)
__global__ void k_build(const int* __restrict__ target) {
    int i = blockIdx.x * blockDim.x + threadIdx.x;
    if (i < BATCH) {
        int t = target[i];
        atomicAdd(&g_counts[t], 1);
        g_next[i] = atomicExch(&g_head[t], i);
    }
}

// K2: fused pass — one warp per class row; last finishing block reduces the
//     loss partials and writes the scalar output (no separate final kernel).
__global__ void __launch_bounds__(256) k_fused(
        const float* __restrict__ features,
        const float* __restrict__ centers,
        float* __restrict__ out_centers,
        float* __restrict__ out_loss) {
    int w    = (blockIdx.x * blockDim.x + threadIdx.x) >> 5;   // class row
    int lane = threadIdx.x & 31;
    int wid  = threadIdx.x >> 5;

    const float* crow = centers + (size_t)w * FEAT_DIM;
    float c[8];
    #pragma unroll
    for (int j = 0; j < 8; j++)
        c[j] = __ldcs(crow + lane + 32 * j);   // 8 independent coalesced loads

    int cnt = g_counts[w];
    float* drow = out_centers + (size_t)w * FEAT_DIM;
    float loss = 0.0f;

    if (cnt == 0) {
        #pragma unroll
        for (int j = 0; j < 8; j++)
            drow[lane + 32 * j] = c[j];
    } else {
        float sumf[8];
        #pragma unroll
        for (int j = 0; j < 8; j++) sumf[j] = 0.0f;

        int s = g_head[w];             // uniform across warp -> no divergence
        while (s >= 0) {
            const float* frow = features + (size_t)s * FEAT_DIM;
            #pragma unroll
            for (int j = 0; j < 8; j++) {
                float f = frow[lane + 32 * j];
                sumf[j] += f;
                float d = c[j] - f;
                loss += d * d;
            }
            s = g_next[s];
        }

        float scale = ALPHA_C / ((float)cnt + EPS_C);
        #pragma unroll
        for (int j = 0; j < 8; j++) {
            float upd = scale * ((float)cnt * c[j] - sumf[j]);
            drow[lane + 32 * j] = c[j] - upd;
        }
    }

    // block-level loss reduction -> one global atomic per block
    __shared__ float warp_sums[8];
    #pragma unroll
    for (int off = 16; off > 0; off >>= 1)
        loss += __shfl_down_sync(0xFFFFFFFFu, loss, off);
    if (lane == 0) warp_sums[wid] = loss;
    __syncthreads();

    __shared__ bool is_last;
    if (threadIdx.x == 0) {
        float b = 0.0f;
        #pragma unroll
        for (int k = 0; k < 8; k++) b += warp_sums[k];
        if (b != 0.0f) atomicAdd(&g_loss_part[blockIdx.x & 255], b);
        __threadfence();
        unsigned int prev = atomicAdd(&g_done, 1u);
        is_last = (prev == (unsigned int)(gridDim.x - 1));
    }
    __syncthreads();

    // last block: reduce the 256 partials in double, write scalar loss
    if (is_last) {
        __shared__ double sh[8];
        double v = (double)g_loss_part[threadIdx.x];
        #pragma unroll
        for (int off = 16; off > 0; off >>= 1)
            v += __shfl_down_sync(0xFFFFFFFFu, v, off);
        if (lane == 0) sh[wid] = v;
        __syncthreads();
        if (wid == 0) {
            double s2 = (lane < 8) ? sh[lane] : 0.0;
            #pragma unroll
            for (int off = 4; off > 0; off >>= 1)
                s2 += __shfl_down_sync(0xFFFFFFFFu, s2, off);
            if (lane == 0)
                out_loss[0] = (float)(s2 / ((double)BATCH * (double)FEAT_DIM));
        }
    }
}

// ---------------------------------------------------------------------------
extern "C" void kernel_launch(void* const* d_in, const int* in_sizes, int n_in,
                              void* d_out, int out_size) {
    const float* features = (const float*)d_in[0];   // [B, D]
    const int*   target   = (const int*)d_in[1];     // [B] (int64 -> int32 on device)
    const float* centers  = (const float*)d_in[2];   // [C, D]

    float* out = (float*)d_out;
    float* out_centers = out + (size_t)out_size - (size_t)NUM_CLASSES * FEAT_DIM;

    k_zero <<<(NUM_CLASSES + 255) / 256, 256>>>();
    k_build<<<(BATCH + 255) / 256, 256>>>(target);
    k_fused<<<FUSED_BLOCKS, 256>>>(features, centers, out_centers, out);
}

// round 6
// speedup vs baseline: 1.4174x; 1.4174x over previous
#include <cuda_runtime.h>
#include <cstdint>

#define NUM_CLASSES 100000
#define FEAT_DIM    256
#define BATCH       8192
#define ALPHA_C     1.0f
#define EPS_C       1e-6f

#define FUSED_BLOCKS (NUM_CLASSES / 8)   // 12500 blocks * 8 warps = 100000 classes

// Scratch — zero-initialized at module load; every kernel restores its own
// scratch to zero after consuming it, so each graph replay starts clean.
__device__ int   g_counts[NUM_CLASSES];  // 0 = untouched class
__device__ int   g_head[NUM_CLASSES];    // 0 = empty; else sample_index+1
__device__ int   g_next[BATCH];          // 0 = end;  else sample_index+1
__device__ float g_loss_part[256];

// ---------------------------------------------------------------------------
// K1: counts + per-class sample linked lists (8192 cheap atomics)
__global__ void k_build(const int* __restrict__ target) {
    int i = blockIdx.x * blockDim.x + threadIdx.x;
    if (i < BATCH) {
        int t = target[i];
        atomicAdd(&g_counts[t], 1);
        g_next[i] = atomicExch(&g_head[t], i + 1);   // 1-based, 0 = empty
    }
}

// K2: fused pass — one warp per class row. Reads+consumes counts/head,
//     zeroing them for the next replay (each slot owned by exactly one warp).
__global__ void __launch_bounds__(256) k_fused(
        const float* __restrict__ features,
        const float* __restrict__ centers,
        float* __restrict__ out_centers) {
    int w    = (blockIdx.x * blockDim.x + threadIdx.x) >> 5;   // class row
    int lane = threadIdx.x & 31;

    const float* crow = centers + (size_t)w * FEAT_DIM;
    float c[8];
    #pragma unroll
    for (int j = 0; j < 8; j++)
        c[j] = __ldcs(crow + lane + 32 * j);   // 8 independent coalesced loads

    int cnt  = g_counts[w];
    int head = g_head[w];
    if (lane == 0 && cnt != 0) {               // self-clean for next replay
        g_counts[w] = 0;
        g_head[w]   = 0;
    }

    float* drow = out_centers + (size_t)w * FEAT_DIM;

    if (cnt == 0) {
        #pragma unroll
        for (int j = 0; j < 8; j++)
            drow[lane + 32 * j] = c[j];
        return;
    }

    float sumf[8];
    #pragma unroll
    for (int j = 0; j < 8; j++) sumf[j] = 0.0f;
    float loss = 0.0f;

    int s = head;                              // uniform across warp
    while (s != 0) {
        const float* frow = features + (size_t)(s - 1) * FEAT_DIM;
        #pragma unroll
        for (int j = 0; j < 8; j++) {
            float f = frow[lane + 32 * j];
            sumf[j] += f;
            float d = c[j] - f;
            loss += d * d;
        }
        s = g_next[s - 1];
    }

    float scale = ALPHA_C / ((float)cnt + EPS_C);
    #pragma unroll
    for (int j = 0; j < 8; j++) {
        float upd = scale * ((float)cnt * c[j] - sumf[j]);
        drow[lane + 32 * j] = c[j] - upd;
    }

    // warp-reduce this row's loss, scatter into 256 partial slots
    #pragma unroll
    for (int off = 16; off > 0; off >>= 1)
        loss += __shfl_down_sync(0xFFFFFFFFu, loss, off);
    if (lane == 0)
        atomicAdd(&g_loss_part[w & 255], loss);
}

// K3: final loss reduce (256 floats -> double -> scalar), self-cleaning
__global__ void k_final(float* __restrict__ out_loss) {
    __shared__ double sh[8];
    int lane = threadIdx.x & 31;
    int wid  = threadIdx.x >> 5;
    double v = (double)g_loss_part[threadIdx.x];
    g_loss_part[threadIdx.x] = 0.0f;           // self-clean for next replay
    #pragma unroll
    for (int off = 16; off > 0; off >>= 1)
        v += __shfl_down_sync(0xFFFFFFFFu, v, off);
    if (lane == 0) sh[wid] = v;
    __syncthreads();
    if (wid == 0) {
        double s = (lane < 8) ? sh[lane] : 0.0;
        #pragma unroll
        for (int off = 4; off > 0; off >>= 1)
            s += __shfl_down_sync(0xFFFFFFFFu, s, off);
        if (lane == 0)
            out_loss[0] = (float)(s / ((double)BATCH * (double)FEAT_DIM));
    }
}

// ---------------------------------------------------------------------------
extern "C" void kernel_launch(void* const* d_in, const int* in_sizes, int n_in,
                              void* d_out, int out_size) {
    const float* features = (const float*)d_in[0];   // [B, D]
    const int*   target   = (const int*)d_in[1];     // [B] (int64 -> int32 on device)
    const float* centers  = (const float*)d_in[2];   // [C, D]

    float* out = (float*)d_out;
    float* out_centers = out + (size_t)out_size - (size_t)NUM_CLASSES * FEAT_DIM;

    k_build<<<(BATCH + 255) / 256, 256>>>(target);
    k_fused<<<FUSED_BLOCKS, 256>>>(features, centers, out_centers);
    k_final<<<1, 256>>>(out);
}